// round 1
// baseline (speedup 1.0000x reference)
#include <cuda_runtime.h>
#include <cuda_fp16.h>
#include <cstdint>

// Problem dims
#define BB    128
#define TT    512
#define DIN   256
#define DH    512
#define G4    2048        // 4*DH
#define DOUT  256
#define NCTA  64          // recurrent CTAs; each owns 8 hidden units (32 gate cols)

// ---------------- static device scratch (no allocs allowed) ----------------
__device__ __half g_x_h[(size_t)BB * TT * DIN];       // x as fp16, [m=t*128+b][k]
__device__ __half g_wx [(size_t)G4 * DIN];            // w_x2h permuted, [p][k]
__device__ __half g_wh [(size_t)G4 * DH];             // w_h2h permuted, [p][k]
__device__ float  g_gbias[G4];                        // b_x2h+b_h2h permuted
__device__ float  g_xg [(size_t)BB * TT * G4];        // xg fp32, [m][p]  (512 MB)
__device__ __half g_hbuf[2][BB * DH];                 // double-buffered h (fp16)
__device__ float  g_hlast[BB * DH];                   // final h in fp32
__device__ int    g_flags[NCTA];

// permuted gate column: p = j*32 + q*8 + u  <->  g = q*512 + j*8 + u
__device__ __forceinline__ int gate_col(int p) {
    return ((p >> 3) & 3) * DH + (p >> 5) * 8 + (p & 7);
}

__device__ __forceinline__ void mma16816(float& d0, float& d1, float& d2, float& d3,
                                         unsigned a0, unsigned a1, unsigned a2, unsigned a3,
                                         unsigned b0, unsigned b1) {
    asm volatile(
        "mma.sync.aligned.m16n8k16.row.col.f32.f16.f16.f32 "
        "{%0,%1,%2,%3}, {%4,%5,%6,%7}, {%8,%9}, {%0,%1,%2,%3};"
        : "+f"(d0), "+f"(d1), "+f"(d2), "+f"(d3)
        : "r"(a0), "r"(a1), "r"(a2), "r"(a3), "r"(b0), "r"(b1));
}

__device__ __forceinline__ float sigm(float x) { return 1.0f / (1.0f + __expf(-x)); }
__device__ __forceinline__ float tanh_a(float x) {
    x = fminf(fmaxf(x, -15.f), 15.f);
    float e = __expf(2.f * x);
    return (e - 1.f) / (e + 1.f);
}
__device__ __forceinline__ float lstm_cell(float zi, float zf, float zg, float zo, float& c) {
    float i = sigm(zi), f = sigm(zf), gg = tanh_a(zg), o = sigm(zo);
    c = fmaf(c, f, i * gg);
    return o * tanh_a(c);
}

// ---------------- prep kernels ----------------
// x[b][t][k] fp32 -> g_x_h[m=t*128+b][k] fp16 (dst-linear, coalesced both sides)
__global__ void prep_x_kernel(const float* __restrict__ x) {
    size_t idx = (size_t)blockIdx.x * 256 + threadIdx.x;   // 16,777,216 exact
    int k = idx & 255;
    int m = (int)(idx >> 8);
    int t = m >> 7, b = m & 127;
    g_x_h[idx] = __float2half_rn(x[((size_t)b * TT + t) * DIN + k]);
}

__global__ void prep_w_kernel(const float* __restrict__ w_x2h, const float* __restrict__ b_x2h,
                              const float* __restrict__ w_h2h, const float* __restrict__ b_h2h) {
    int idx = blockIdx.x * 256 + threadIdx.x;   // 1,048,576 exact = 2048*512
    {   // w_h2h: g_wh[p*512+k] = w_h2h[k][gc(p)]
        int p = idx >> 9, k = idx & 511;
        g_wh[idx] = __float2half_rn(w_h2h[(size_t)k * G4 + gate_col(p)]);
    }
    if (idx < G4 * DIN) {  // w_x2h: g_wx[p*256+k]
        int p = idx >> 8, k = idx & 255;
        g_wx[idx] = __float2half_rn(w_x2h[(size_t)k * G4 + gate_col(p)]);
    }
    if (idx < G4) {
        int gc = gate_col(idx);
        g_gbias[idx] = b_x2h[gc] + b_h2h[gc];
    }
    if (idx < NCTA) g_flags[idx] = 0;
}

// ---------------- GEMM1: xg[m][p] = x_h[m][:] @ wx[p][:] + gbias[p] ----------------
// tile 128x64, K=256, 256 threads, 8 warps x (16 rows x 64 cols)
#define G1_SMEM ((128 * 264 + 64 * 264) * 2)
__global__ __launch_bounds__(256, 1) void gemm1_kernel() {
    extern __shared__ __half sm[];
    __half* x_sm = sm;                 // 128 x 264 (K=256 + pad 8)
    __half* w_sm = sm + 128 * 264;     // 64  x 264
    const int tid = threadIdx.x;
    const int m0 = blockIdx.y * 128, n0 = blockIdx.x * 64;

    const uint4* xs = (const uint4*)g_x_h;
    #pragma unroll 4
    for (int i = tid; i < 4096; i += 256) {            // 128 rows x 32 uint4
        int r = i >> 5, k8 = (i & 31) << 3;
        *(uint4*)&x_sm[r * 264 + k8] = xs[(size_t)(m0 + r) * 32 + (i & 31)];
    }
    const uint4* ws = (const uint4*)g_wx;
    #pragma unroll 4
    for (int i = tid; i < 2048; i += 256) {            // 64 rows x 32 uint4
        int c = i >> 5, k8 = (i & 31) << 3;
        *(uint4*)&w_sm[c * 264 + k8] = ws[(size_t)(n0 + c) * 32 + (i & 31)];
    }
    __syncthreads();

    const int w = tid >> 5, lane = tid & 31, g = lane >> 2, q = lane & 3;
    const int r0 = 16 * w + g;
    float acc[8][4];
    #pragma unroll
    for (int nt = 0; nt < 8; nt++) { acc[nt][0] = acc[nt][1] = acc[nt][2] = acc[nt][3] = 0.f; }

    #pragma unroll 4
    for (int kt = 0; kt < 16; kt++) {
        int k0 = kt * 16 + 2 * q;
        unsigned a0 = *(const unsigned*)&x_sm[r0 * 264 + k0];
        unsigned a1 = *(const unsigned*)&x_sm[(r0 + 8) * 264 + k0];
        unsigned a2 = *(const unsigned*)&x_sm[r0 * 264 + k0 + 8];
        unsigned a3 = *(const unsigned*)&x_sm[(r0 + 8) * 264 + k0 + 8];
        #pragma unroll
        for (int nt = 0; nt < 8; nt++) {
            unsigned b0 = *(const unsigned*)&w_sm[(8 * nt + g) * 264 + k0];
            unsigned b1 = *(const unsigned*)&w_sm[(8 * nt + g) * 264 + k0 + 8];
            mma16816(acc[nt][0], acc[nt][1], acc[nt][2], acc[nt][3], a0, a1, a2, a3, b0, b1);
        }
    }
    #pragma unroll
    for (int nt = 0; nt < 8; nt++) {
        int p = n0 + 8 * nt + 2 * q;
        float2 gb = *(const float2*)&g_gbias[p];
        float2 v0 = make_float2(acc[nt][0] + gb.x, acc[nt][1] + gb.y);
        float2 v1 = make_float2(acc[nt][2] + gb.x, acc[nt][3] + gb.y);
        *(float2*)&g_xg[(size_t)(m0 + r0) * G4 + p]     = v0;
        *(float2*)&g_xg[(size_t)(m0 + r0 + 8) * G4 + p] = v1;
    }
}

// ---------------- persistent recurrent kernel ----------------
// 64 CTAs, 256 thr. CTA j owns hidden units j*8..j*8+7 (32 gate cols).
// SMEM: h (128x520 halves) + weights (32x520 halves) = 166,400 B
#define REC_SMEM ((128 * 520 + 32 * 520) * 2)
__global__ __launch_bounds__(256, 1) void rec_kernel() {
    extern __shared__ __half sm[];
    __half* h_sm = sm;               // 128 x 520
    __half* w_sm = sm + 128 * 520;   // 32  x 520
    const int tid = threadIdx.x;
    const int j = blockIdx.x;
    const int w = tid >> 5, lane = tid & 31, g = lane >> 2, q = lane & 3;
    const int r0 = 16 * w + g, r1 = r0 + 8;
    const int colbase = j * 32;

    // stationary weights -> smem (once)
    const uint4* ws = (const uint4*)(g_wh + (size_t)j * 32 * DH);
    #pragma unroll 4
    for (int i = tid; i < 2048; i += 256) {          // 32 rows x 64 uint4
        int c = i >> 6, k8 = (i & 63) << 3;
        *(uint4*)&w_sm[c * 520 + k8] = ws[i];
    }
    __syncthreads();

    float c00 = 0.f, c01 = 0.f, c10 = 0.f, c11 = 0.f;   // cell state, resident

    for (int t = 0; t < TT; t++) {
        // prefetch xg for this step (independent of the wait)
        const float* xg0 = g_xg + ((size_t)(t * BB + r0)) * G4 + colbase + 2 * q;
        const float* xg1 = g_xg + ((size_t)(t * BB + r1)) * G4 + colbase + 2 * q;
        float2 xr0[4], xr1[4];
        #pragma unroll
        for (int nt = 0; nt < 4; nt++) {
            xr0[nt] = *(const float2*)(xg0 + nt * 8);
            xr1[nt] = *(const float2*)(xg1 + nt * 8);
        }

        float acc[4][4];
        #pragma unroll
        for (int nt = 0; nt < 4; nt++) { acc[nt][0] = acc[nt][1] = acc[nt][2] = acc[nt][3] = 0.f; }

        if (t > 0) {
            // acquire: all CTAs have published h(t)
            if (tid < NCTA) {
                volatile int* fl = g_flags + tid;
                while (*fl < t) { }
            }
            __threadfence();
            __syncthreads();

            // h(t) -> smem (L2-coherent loads; L1 may hold stale lines)
            const uint4* hsrc = (const uint4*)(g_hbuf[t & 1]);
            #pragma unroll 8
            for (int i2 = 0; i2 < 32; i2++) {
                int i = tid + i2 * 256;
                int m = i >> 6, k8 = (i & 63) << 3;
                uint4 v = __ldcg(hsrc + i);
                *(uint4*)&h_sm[m * 520 + k8] = v;
            }
            __syncthreads();

            // gates += h @ W   (M=128, N=32, K=512)
            #pragma unroll 8
            for (int kt = 0; kt < 32; kt++) {
                int k0 = kt * 16 + 2 * q;
                unsigned a0 = *(const unsigned*)&h_sm[r0 * 520 + k0];
                unsigned a1 = *(const unsigned*)&h_sm[r1 * 520 + k0];
                unsigned a2 = *(const unsigned*)&h_sm[r0 * 520 + k0 + 8];
                unsigned a3 = *(const unsigned*)&h_sm[r1 * 520 + k0 + 8];
                #pragma unroll
                for (int nt = 0; nt < 4; nt++) {
                    unsigned b0 = *(const unsigned*)&w_sm[(8 * nt + g) * 520 + k0];
                    unsigned b1 = *(const unsigned*)&w_sm[(8 * nt + g) * 520 + k0 + 8];
                    mma16816(acc[nt][0], acc[nt][1], acc[nt][2], acc[nt][3], a0, a1, a2, a3, b0, b1);
                }
            }
        }

        // elementwise cell: each thread has all 4 gates for 2 rows x 2 hidden units
        float h00 = lstm_cell(acc[0][0] + xr0[0].x, acc[1][0] + xr0[1].x,
                              acc[2][0] + xr0[2].x, acc[3][0] + xr0[3].x, c00);
        float h01 = lstm_cell(acc[0][1] + xr0[0].y, acc[1][1] + xr0[1].y,
                              acc[2][1] + xr0[2].y, acc[3][1] + xr0[3].y, c01);
        float h10 = lstm_cell(acc[0][2] + xr1[0].x, acc[1][2] + xr1[1].x,
                              acc[2][2] + xr1[2].x, acc[3][2] + xr1[3].x, c10);
        float h11 = lstm_cell(acc[0][3] + xr1[0].y, acc[1][3] + xr1[1].y,
                              acc[2][3] + xr1[2].y, acc[3][3] + xr1[3].y, c11);

        __half* hd = g_hbuf[(t + 1) & 1];
        int hoff = j * 8 + 2 * q;
        *(half2*)(hd + r0 * DH + hoff) = __floats2half2_rn(h00, h01);
        *(half2*)(hd + r1 * DH + hoff) = __floats2half2_rn(h10, h11);
        if (t == TT - 1) {
            *(float2*)&g_hlast[r0 * DH + hoff] = make_float2(h00, h01);
            *(float2*)&g_hlast[r1 * DH + hoff] = make_float2(h10, h11);
        }

        __threadfence();        // release h(t+1)
        __syncthreads();        // all threads' h writes done; h_sm reusable
        if (tid == 0) atomicExch(&g_flags[j], t + 1);
    }
}

// ---------------- final FC: out = hlast @ w_fc + b_fc (fp32) ----------------
__global__ void fc_kernel(const float* __restrict__ w_fc, const float* __restrict__ b_fc,
                          float* __restrict__ out) {
    __shared__ float hs[DH];
    int b = blockIdx.x, o = threadIdx.x;
    for (int i = o; i < DH; i += 256) hs[i] = g_hlast[b * DH + i];
    __syncthreads();
    float acc = b_fc[o];
    #pragma unroll 8
    for (int k = 0; k < DH; k++) acc = fmaf(hs[k], w_fc[(size_t)k * DOUT + o], acc);
    out[b * DOUT + o] = acc;
}

// ---------------- launch ----------------
extern "C" void kernel_launch(void* const* d_in, const int* in_sizes, int n_in,
                              void* d_out, int out_size) {
    (void)in_sizes; (void)n_in; (void)out_size;
    const float* x     = (const float*)d_in[0];
    const float* w_x2h = (const float*)d_in[1];
    const float* b_x2h = (const float*)d_in[2];
    const float* w_h2h = (const float*)d_in[3];
    const float* b_h2h = (const float*)d_in[4];
    const float* w_fc  = (const float*)d_in[5];
    const float* b_fc  = (const float*)d_in[6];
    float* out = (float*)d_out;

    cudaFuncSetAttribute(gemm1_kernel, cudaFuncAttributeMaxDynamicSharedMemorySize, G1_SMEM);
    cudaFuncSetAttribute(rec_kernel,   cudaFuncAttributeMaxDynamicSharedMemorySize, REC_SMEM);

    prep_x_kernel<<<65536, 256>>>(x);
    prep_w_kernel<<<4096, 256>>>(w_x2h, b_x2h, w_h2h, b_h2h);
    gemm1_kernel<<<dim3(32, 512), 256, G1_SMEM>>>();
    rec_kernel<<<NCTA, 256, REC_SMEM>>>();
    fc_kernel<<<BB, 256>>>(w_fc, b_fc, out);
}

// round 2
// speedup vs baseline: 1.4499x; 1.4499x over previous
#include <cuda_runtime.h>
#include <cuda_fp16.h>
#include <cstdint>

// Problem dims
#define BB    128
#define TT    512
#define DIN   256
#define DH    512
#define G4    2048        // 4*DH
#define DOUT  256
#define RCTA  128         // recurrent CTAs = 8 batch-groups x 16 col-groups

// ---------------- static device scratch (no allocs allowed) ----------------
__device__ __half g_x_h[(size_t)BB * TT * DIN];       // x as fp16, [m=t*128+b][k]
__device__ __half g_wx [(size_t)G4 * DIN];            // w_x2h permuted, [p][k]
__device__ __half g_wh [(size_t)G4 * DH];            // w_h2h permuted, [p][k]
__device__ float  g_gbias[G4];                        // b_x2h+b_h2h permuted
__device__ float  g_xg [(size_t)BB * TT * G4];        // xg fp32, [m][p]
__device__ __half g_hbuf[2][BB * DH];                 // double-buffered h (fp16)
__device__ float  g_hlast[BB * DH];                   // final h in fp32
__device__ int    g_flags[RCTA];

// permuted gate column: p = cg*128 + w4*32 + q*8 + u
//   cg = p>>7 (colgroup 0..15), w4 = (p>>5)&3, q = gate 0..3, u = unit 0..7
// original gate col g = q*512 + cg*32 + w4*8 + u   (hidden unit = cg*32+w4*8+u)
__device__ __forceinline__ int gate_col(int p) {
    return ((p >> 3) & 3) * DH + (p >> 7) * 32 + (((p >> 5) & 3) << 3) + (p & 7);
}

__device__ __forceinline__ void mma16816(float& d0, float& d1, float& d2, float& d3,
                                         unsigned a0, unsigned a1, unsigned a2, unsigned a3,
                                         unsigned b0, unsigned b1) {
    asm volatile(
        "mma.sync.aligned.m16n8k16.row.col.f32.f16.f16.f32 "
        "{%0,%1,%2,%3}, {%4,%5,%6,%7}, {%8,%9}, {%0,%1,%2,%3};"
        : "+f"(d0), "+f"(d1), "+f"(d2), "+f"(d3)
        : "r"(a0), "r"(a1), "r"(a2), "r"(a3), "r"(b0), "r"(b1));
}

__device__ __forceinline__ float sigm(float x) { return 1.0f / (1.0f + __expf(-x)); }
__device__ __forceinline__ float tanh_a(float x) {
    x = fminf(fmaxf(x, -15.f), 15.f);
    float e = __expf(2.f * x);
    return (e - 1.f) / (e + 1.f);
}
__device__ __forceinline__ float lstm_cell(float zi, float zf, float zg, float zo, float& c) {
    float i = sigm(zi), f = sigm(zf), gg = tanh_a(zg), o = sigm(zo);
    c = fmaf(c, f, i * gg);
    return o * tanh_a(c);
}

// ---------------- prep kernels ----------------
__global__ void prep_x_kernel(const float* __restrict__ x) {
    size_t idx = (size_t)blockIdx.x * 256 + threadIdx.x;   // 16,777,216 exact
    int k = idx & 255;
    int m = (int)(idx >> 8);
    int t = m >> 7, b = m & 127;
    g_x_h[idx] = __float2half_rn(x[((size_t)b * TT + t) * DIN + k]);
}

__global__ void prep_w_kernel(const float* __restrict__ w_x2h, const float* __restrict__ b_x2h,
                              const float* __restrict__ w_h2h, const float* __restrict__ b_h2h) {
    int idx = blockIdx.x * 256 + threadIdx.x;   // 1,048,576 exact = 2048*512
    {   // w_h2h: g_wh[p*512+k] = w_h2h[k][gc(p)]
        int p = idx >> 9, k = idx & 511;
        g_wh[idx] = __float2half_rn(w_h2h[(size_t)k * G4 + gate_col(p)]);
    }
    if (idx < G4 * DIN) {  // w_x2h: g_wx[p*256+k]
        int p = idx >> 8, k = idx & 255;
        g_wx[idx] = __float2half_rn(w_x2h[(size_t)k * G4 + gate_col(p)]);
    }
    if (idx < G4) {
        int gc = gate_col(idx);
        g_gbias[idx] = b_x2h[gc] + b_h2h[gc];
    }
    if (idx < RCTA) g_flags[idx] = 0;
}

// ---------------- GEMM1: xg[m][p] = x_h[m][:] @ wx[p][:] + gbias[p] ----------------
#define G1_SMEM ((128 * 264 + 64 * 264) * 2)
__global__ __launch_bounds__(256, 1) void gemm1_kernel() {
    extern __shared__ __half sm[];
    __half* x_sm = sm;                 // 128 x 264 (K=256 + pad 8)
    __half* w_sm = sm + 128 * 264;     // 64  x 264
    const int tid = threadIdx.x;
    const int m0 = blockIdx.y * 128, n0 = blockIdx.x * 64;

    const uint4* xs = (const uint4*)g_x_h;
    #pragma unroll 4
    for (int i = tid; i < 4096; i += 256) {            // 128 rows x 32 uint4
        int r = i >> 5, k8 = (i & 31) << 3;
        *(uint4*)&x_sm[r * 264 + k8] = xs[(size_t)(m0 + r) * 32 + (i & 31)];
    }
    const uint4* ws = (const uint4*)g_wx;
    #pragma unroll 4
    for (int i = tid; i < 2048; i += 256) {            // 64 rows x 32 uint4
        int c = i >> 5, k8 = (i & 31) << 3;
        *(uint4*)&w_sm[c * 264 + k8] = ws[(size_t)(n0 + c) * 32 + (i & 31)];
    }
    __syncthreads();

    const int w = tid >> 5, lane = tid & 31, g = lane >> 2, q = lane & 3;
    const int r0 = 16 * w + g;
    float acc[8][4];
    #pragma unroll
    for (int nt = 0; nt < 8; nt++) { acc[nt][0] = acc[nt][1] = acc[nt][2] = acc[nt][3] = 0.f; }

    #pragma unroll 4
    for (int kt = 0; kt < 16; kt++) {
        int k0 = kt * 16 + 2 * q;
        unsigned a0 = *(const unsigned*)&x_sm[r0 * 264 + k0];
        unsigned a1 = *(const unsigned*)&x_sm[(r0 + 8) * 264 + k0];
        unsigned a2 = *(const unsigned*)&x_sm[r0 * 264 + k0 + 8];
        unsigned a3 = *(const unsigned*)&x_sm[(r0 + 8) * 264 + k0 + 8];
        #pragma unroll
        for (int nt = 0; nt < 8; nt++) {
            unsigned b0 = *(const unsigned*)&w_sm[(8 * nt + g) * 264 + k0];
            unsigned b1 = *(const unsigned*)&w_sm[(8 * nt + g) * 264 + k0 + 8];
            mma16816(acc[nt][0], acc[nt][1], acc[nt][2], acc[nt][3], a0, a1, a2, a3, b0, b1);
        }
    }
    #pragma unroll
    for (int nt = 0; nt < 8; nt++) {
        int p = n0 + 8 * nt + 2 * q;
        float2 gb = *(const float2*)&g_gbias[p];
        float2 v0 = make_float2(acc[nt][0] + gb.x, acc[nt][1] + gb.y);
        float2 v1 = make_float2(acc[nt][2] + gb.x, acc[nt][3] + gb.y);
        *(float2*)&g_xg[(size_t)(m0 + r0) * G4 + p]     = v0;
        *(float2*)&g_xg[(size_t)(m0 + r0 + 8) * G4 + p] = v1;
    }
}

// ---------------- persistent recurrent kernel (2-D partition) ----------------
// 128 CTAs = 8 batch-groups (16 rows each) x 16 col-groups (128 gate cols each).
// SMEM: W 128x520 halves + h 16x520 halves + splitK reduce 128x17 floats
#define REC_SMEM ((128 * 520 + 16 * 520) * 2 + 128 * 17 * 4)
__global__ __launch_bounds__(256, 1) void rec_kernel() {
    extern __shared__ unsigned char smraw[];
    __half* w_sm = (__half*)smraw;                          // 128 x 520
    __half* h_sm = (__half*)(smraw + 128 * 520 * 2);        // 16 x 520
    float*  red  = (float*)(smraw + (128 * 520 + 16 * 520) * 2); // [128][17]

    const int tid = threadIdx.x;
    const int j = blockIdx.x;
    const int bg = j >> 4, cg = j & 15;
    const int w = tid >> 5, lane = tid & 31;
    const int g = lane >> 2, q = lane & 3;
    const int w4 = w & 3, kh = w >> 2;     // colgroup-in-CTA, K-half
    const int r0 = g, r1 = g + 8;          // rows within 16-row tile

    // stationary weights -> smem (once): cols [cg*128, +128), K=512
    const uint4* ws = (const uint4*)(g_wh + (size_t)cg * 128 * DH);
    #pragma unroll 8
    for (int i = tid; i < 8192; i += 256) {          // 128 rows x 64 uint4
        int c = i >> 6, k8 = (i & 63) << 3;
        *(uint4*)&w_sm[c * 520 + k8] = ws[i];
    }
    __syncthreads();

    float c00 = 0.f, c01 = 0.f, c10 = 0.f, c11 = 0.f;   // cell state (warps 0-3)

    for (int t = 0; t < TT; t++) {
        // prefetch xg for this step (warps 0-3; independent of the wait)
        float2 xr0[4], xr1[4];
        if (w < 4) {
            const float* xg0 = g_xg + ((size_t)(t * BB + bg * 16 + r0)) * G4
                               + cg * 128 + w4 * 32 + 2 * q;
            const float* xg1 = xg0 + (size_t)8 * G4;
            #pragma unroll
            for (int nt = 0; nt < 4; nt++) {
                xr0[nt] = *(const float2*)(xg0 + nt * 8);
                xr1[nt] = *(const float2*)(xg1 + nt * 8);
            }
        }

        float acc[4][4];
        #pragma unroll
        for (int nt = 0; nt < 4; nt++) { acc[nt][0] = acc[nt][1] = acc[nt][2] = acc[nt][3] = 0.f; }

        if (t > 0) {
            // acquire: the 16 CTAs of this batch group published h(t)
            if (tid < 16) {
                volatile int* fl = g_flags + bg * 16 + tid;
                while (*fl < t) { }
            }
            __threadfence();
            __syncthreads();

            // h(t) rows [bg*16, +16) -> smem  (16 KB, L2-coherent loads)
            const uint4* hsrc = (const uint4*)(g_hbuf[t & 1]) + (size_t)bg * 16 * (DH / 8);
            #pragma unroll
            for (int it = 0; it < 4; it++) {
                int i = tid + it * 256;                  // 1024 uint4 total
                int m = i >> 6, k8 = (i & 63) << 3;
                uint4 v = __ldcg(hsrc + i);
                *(uint4*)&h_sm[m * 520 + k8] = v;
            }
            __syncthreads();

            // gates += h @ W   (M=16, N=32 per warp-colgroup, split-K halves)
            #pragma unroll
            for (int kt = 0; kt < 16; kt++) {
                int k0 = kh * 256 + kt * 16 + 2 * q;
                unsigned a0 = *(const unsigned*)&h_sm[r0 * 520 + k0];
                unsigned a1 = *(const unsigned*)&h_sm[r1 * 520 + k0];
                unsigned a2 = *(const unsigned*)&h_sm[r0 * 520 + k0 + 8];
                unsigned a3 = *(const unsigned*)&h_sm[r1 * 520 + k0 + 8];
                #pragma unroll
                for (int nt = 0; nt < 4; nt++) {
                    const __half* wb = &w_sm[(w4 * 32 + nt * 8 + g) * 520 + k0];
                    unsigned b0 = *(const unsigned*)wb;
                    unsigned b1 = *(const unsigned*)(wb + 8);
                    mma16816(acc[nt][0], acc[nt][1], acc[nt][2], acc[nt][3], a0, a1, a2, a3, b0, b1);
                }
            }

            // split-K reduction: warps 4-7 hand partials to warps 0-3
            if (kh == 1) {
                float* rp = red + (w4 * 32 + lane) * 17;
                #pragma unroll
                for (int nt = 0; nt < 4; nt++) {
                    #pragma unroll
                    for (int e = 0; e < 4; e++) rp[nt * 4 + e] = acc[nt][e];
                }
            }
            __syncthreads();
            if (kh == 0) {
                const float* rp = red + (w4 * 32 + lane) * 17;
                #pragma unroll
                for (int nt = 0; nt < 4; nt++) {
                    #pragma unroll
                    for (int e = 0; e < 4; e++) acc[nt][e] += rp[nt * 4 + e];
                }
            }
        }

        if (w < 4) {
            // each thread has all 4 gates for 2 rows x 2 hidden units
            float h00 = lstm_cell(acc[0][0] + xr0[0].x, acc[1][0] + xr0[1].x,
                                  acc[2][0] + xr0[2].x, acc[3][0] + xr0[3].x, c00);
            float h01 = lstm_cell(acc[0][1] + xr0[0].y, acc[1][1] + xr0[1].y,
                                  acc[2][1] + xr0[2].y, acc[3][1] + xr0[3].y, c01);
            float h10 = lstm_cell(acc[0][2] + xr1[0].x, acc[1][2] + xr1[1].x,
                                  acc[2][2] + xr1[2].x, acc[3][2] + xr1[3].x, c10);
            float h11 = lstm_cell(acc[0][3] + xr1[0].y, acc[1][3] + xr1[1].y,
                                  acc[2][3] + xr1[2].y, acc[3][3] + xr1[3].y, c11);

            __half* hd = g_hbuf[(t + 1) & 1];
            int row0 = bg * 16 + r0, row1 = row0 + 8;
            int hoff = cg * 32 + w4 * 8 + 2 * q;
            *(half2*)(hd + row0 * DH + hoff) = __floats2half2_rn(h00, h01);
            *(half2*)(hd + row1 * DH + hoff) = __floats2half2_rn(h10, h11);
            if (t == TT - 1) {
                *(float2*)&g_hlast[row0 * DH + hoff] = make_float2(h00, h01);
                *(float2*)&g_hlast[row1 * DH + hoff] = make_float2(h10, h11);
            }
        }

        __threadfence();        // release h(t+1)
        __syncthreads();
        if (tid == 0) atomicExch(&g_flags[j], t + 1);
    }
}

// ---------------- final FC: out = hlast @ w_fc + b_fc (fp32) ----------------
__global__ void fc_kernel(const float* __restrict__ w_fc, const float* __restrict__ b_fc,
                          float* __restrict__ out) {
    __shared__ float hs[DH];
    int b = blockIdx.x, o = threadIdx.x;
    for (int i = o; i < DH; i += 256) hs[i] = g_hlast[b * DH + i];
    __syncthreads();
    float acc = b_fc[o];
    #pragma unroll 8
    for (int k = 0; k < DH; k++) acc = fmaf(hs[k], w_fc[(size_t)k * DOUT + o], acc);
    out[b * DOUT + o] = acc;
}

// ---------------- launch ----------------
extern "C" void kernel_launch(void* const* d_in, const int* in_sizes, int n_in,
                              void* d_out, int out_size) {
    (void)in_sizes; (void)n_in; (void)out_size;
    const float* x     = (const float*)d_in[0];
    const float* w_x2h = (const float*)d_in[1];
    const float* b_x2h = (const float*)d_in[2];
    const float* w_h2h = (const float*)d_in[3];
    const float* b_h2h = (const float*)d_in[4];
    const float* w_fc  = (const float*)d_in[5];
    const float* b_fc  = (const float*)d_in[6];
    float* out = (float*)d_out;

    cudaFuncSetAttribute(gemm1_kernel, cudaFuncAttributeMaxDynamicSharedMemorySize, G1_SMEM);
    cudaFuncSetAttribute(rec_kernel,   cudaFuncAttributeMaxDynamicSharedMemorySize, REC_SMEM);

    prep_x_kernel<<<65536, 256>>>(x);
    prep_w_kernel<<<4096, 256>>>(w_x2h, b_x2h, w_h2h, b_h2h);
    gemm1_kernel<<<dim3(32, 512), 256, G1_SMEM>>>();
    rec_kernel<<<RCTA, 256, REC_SMEM>>>();
    fc_kernel<<<BB, 256>>>(w_fc, b_fc, out);
}